// round 6
// baseline (speedup 1.0000x reference)
#include <cuda_runtime.h>
#include <cuda_fp16.h>
#include <cstdint>
#include <cstddef>

#define BATCH 32768
#define IN_F  512
#define OUT_F 512
#define KP    4096             // K' = IN_F * 8  (d = 1..8; d=0 folded into bias)

#define BM 128
#define BN 256
#define BK 64
#define NITER (KP / BK)        // 64
#define COEF_SCALE 4096.0f
#define OUT_SCALE  (1.0f / 4096.0f)

// ---------------- smem layout (bytes) ----------------------------------------
// B stages:   2 x 32768           [0, 65536)
// A bufs:     2 x 16384           [65536, 98304)
// u  (fp32):  128 rows x 272B     [98304, 133120)
// T0 (fp32):  128 rows x 272B     [133120, 167936)
// T1 (fp32):  128 rows x 272B     [167936, 202752)
#define OFF_B(s) ((s) * 32768u)
#define OFF_A(p) (65536u + (p) * 16384u)
#define OFF_U    98304u
#define OFF_T0   133120u
#define OFF_T1   167936u
#define SMEM_TOTAL 202752

// ---------------- scratch ----------------------------------------------------
__device__ __align__(1024) __half g_B[(size_t)OUT_F * KP];   // 4 MB
__device__ float g_bias[OUT_F];

// ---------------- helpers ----------------------------------------------------
__device__ __forceinline__ uint32_t smem_u32(const void* p) {
    uint32_t a;
    asm("{ .reg .u64 t; cvta.to.shared.u64 t, %1; cvt.u32.u64 %0, t; }" : "=r"(a) : "l"(p));
    return a;
}
__device__ __forceinline__ uint32_t pack_h2(float lo, float hi) {
    uint32_t r;
    asm("cvt.rn.f16x2.f32 %0, %1, %2;" : "=r"(r) : "f"(hi), "f"(lo));
    return r;
}
__device__ __forceinline__ void cp_async16(uint32_t dst, const void* src) {
    asm volatile("cp.async.cg.shared.global [%0], [%1], 16;" :: "r"(dst), "l"(src) : "memory");
}
#define CP_COMMIT() asm volatile("cp.async.commit_group;" ::: "memory")
#define CP_WAIT(n)  asm volatile("cp.async.wait_group %0;" :: "n"(n) : "memory")

__device__ __forceinline__ void ldsm_x4(uint32_t f[4], uint32_t addr) {
    asm volatile("ldmatrix.sync.aligned.m8n8.x4.shared.b16 {%0,%1,%2,%3}, [%4];"
                 : "=r"(f[0]), "=r"(f[1]), "=r"(f[2]), "=r"(f[3]) : "r"(addr));
}
__device__ __forceinline__ void mma16816(float c[4], const uint32_t a[4],
                                         uint32_t b0, uint32_t b1) {
    asm volatile(
        "mma.sync.aligned.m16n8k16.row.col.f32.f16.f16.f32 "
        "{%0,%1,%2,%3}, {%4,%5,%6,%7}, {%8,%9}, {%0,%1,%2,%3};"
        : "+f"(c[0]), "+f"(c[1]), "+f"(c[2]), "+f"(c[3])
        : "r"(a[0]), "r"(a[1]), "r"(a[2]), "r"(a[3]), "r"(b0), "r"(b1));
}

// ---------------- gen_b: B'[o, iblk*512+(d-1)*64+ii] = 4096*C[i,o,d]; bias ---
__global__ void gen_b_kernel(const float* __restrict__ c, __half* __restrict__ B,
                             float* __restrict__ bias) {
    __shared__ float red[IN_F];
    int o = blockIdx.x;
    int i = threadIdx.x;                  // 0..511
    const float* src = c + ((size_t)i * OUT_F + o) * 9;
    float c0 = src[0];
    red[i] = c0;
    __half* dst = B + (size_t)o * KP + (i >> 6) * 512 + (i & 63);
#pragma unroll
    for (int d = 1; d <= 8; d++)
        dst[(d - 1) * 64] = __float2half_rn(src[d] * COEF_SCALE);
    __syncthreads();
#pragma unroll
    for (int s = IN_F / 2; s > 0; s >>= 1) {
        if (i < s) red[i] += red[i + s];
        __syncthreads();
    }
    if (i == 0) bias[o] = red[0] * COEF_SCALE;
}

// ---------------- A-chunk generation (in-GEMM) -------------------------------
// chunk c1: iblk = c1>>3, d = (c1&7)+1.  A[m][ii] = T_d(tanh(x[m0+m][iblk*64+ii]))
// thread -> m = tid&127, j = (tid>>7)*4 + r (r=0..3), j = ii oct (8 values)
__device__ __forceinline__ void gen_chunk(char* sm, const float* __restrict__ xg,
                                          int c1, int m0) {
    int tid = threadIdx.x;
    int m  = tid & 127;
    int jb = (tid >> 7) * 4;
    int d    = (c1 & 7) + 1;
    int iblk = c1 >> 3;
    char* arow = sm + OFF_A(c1 & 1) + m * 128;
    char* urow = sm + OFF_U  + m * 272;
    char* b0row = sm + OFF_T0 + m * 272;
    char* b1row = sm + OFF_T1 + m * 272;
    if (d == 1) {
        const float* xp = xg + (size_t)(m0 + m) * IN_F + iblk * 64;
#pragma unroll
        for (int r = 0; r < 4; r++) {
            int j = jb + r;
            float4 xa = *reinterpret_cast<const float4*>(xp + j * 8);
            float4 xb = *reinterpret_cast<const float4*>(xp + j * 8 + 4);
            float4 ua, ub;
            ua.x = tanhf(xa.x); ua.y = tanhf(xa.y); ua.z = tanhf(xa.z); ua.w = tanhf(xa.w);
            ub.x = tanhf(xb.x); ub.y = tanhf(xb.y); ub.z = tanhf(xb.z); ub.w = tanhf(xb.w);
            *reinterpret_cast<float4*>(urow + j * 32)      = ua;
            *reinterpret_cast<float4*>(urow + j * 32 + 16) = ub;
            // Tc = T_1 = u lives in buf[(d)&1] = buf1 ; Tp = T_0 = 1 in buf0
            *reinterpret_cast<float4*>(b1row + j * 32)      = ua;
            *reinterpret_cast<float4*>(b1row + j * 32 + 16) = ub;
            float4 ones = make_float4(1.f, 1.f, 1.f, 1.f);
            *reinterpret_cast<float4*>(b0row + j * 32)      = ones;
            *reinterpret_cast<float4*>(b0row + j * 32 + 16) = ones;
            uint4 h;
            h.x = pack_h2(ua.x, ua.y);
            h.y = pack_h2(ua.z, ua.w);
            h.z = pack_h2(ub.x, ub.y);
            h.w = pack_h2(ub.z, ub.w);
            *reinterpret_cast<uint4*>(arow + ((j ^ (m & 7)) << 4)) = h;
        }
    } else {
        // read Tc = buf[(d-1)&1], Tp = buf[d&1]; write Tnext over Tp
        char* tcrow = ((d - 1) & 1) ? b1row : b0row;
        char* tprow = (d & 1) ? b1row : b0row;
#pragma unroll
        for (int r = 0; r < 4; r++) {
            int j = jb + r;
            float4 ua = *reinterpret_cast<const float4*>(urow + j * 32);
            float4 ub = *reinterpret_cast<const float4*>(urow + j * 32 + 16);
            float4 ca = *reinterpret_cast<const float4*>(tcrow + j * 32);
            float4 cb = *reinterpret_cast<const float4*>(tcrow + j * 32 + 16);
            float4 pa = *reinterpret_cast<const float4*>(tprow + j * 32);
            float4 pb = *reinterpret_cast<const float4*>(tprow + j * 32 + 16);
            float4 na, nb;
            na.x = __fmaf_rn(2.f * ua.x, ca.x, -pa.x);
            na.y = __fmaf_rn(2.f * ua.y, ca.y, -pa.y);
            na.z = __fmaf_rn(2.f * ua.z, ca.z, -pa.z);
            na.w = __fmaf_rn(2.f * ua.w, ca.w, -pa.w);
            nb.x = __fmaf_rn(2.f * ub.x, cb.x, -pb.x);
            nb.y = __fmaf_rn(2.f * ub.y, cb.y, -pb.y);
            nb.z = __fmaf_rn(2.f * ub.z, cb.z, -pb.z);
            nb.w = __fmaf_rn(2.f * ub.w, cb.w, -pb.w);
            *reinterpret_cast<float4*>(tprow + j * 32)      = na;
            *reinterpret_cast<float4*>(tprow + j * 32 + 16) = nb;
            uint4 h;
            h.x = pack_h2(na.x, na.y);
            h.y = pack_h2(na.z, na.w);
            h.z = pack_h2(nb.x, nb.y);
            h.w = pack_h2(nb.z, nb.w);
            *reinterpret_cast<uint4*>(arow + ((j ^ (m & 7)) << 4)) = h;
        }
    }
}

// ---------------- fused GEMM: M=32768 N=512 K'=4096 --------------------------
__global__ __launch_bounds__(256, 1)
void gemm_kernel(const float* __restrict__ x, const __half* __restrict__ Bw,
                 const float* __restrict__ bias, float* __restrict__ out) {
    extern __shared__ __align__(1024) char smem[];
    uint32_t sb = smem_u32(smem);
    int tid = threadIdx.x;
    int wid = tid >> 5, lid = tid & 31;
    int m0 = blockIdx.y * BM;
    int n0 = blockIdx.x * BN;
    int wm = wid & 3, wn = wid >> 2;

    // acc init = bias (T_0 contribution, already scaled by 4096)
    float acc[2][16][4];
    {
        int ncol = (lid & 3) * 2;
#pragma unroll
        for (int ni = 0; ni < 16; ni++) {
            int n = n0 + wn * 128 + ni * 8 + ncol;
            float b0 = __ldg(bias + n);
            float b1 = __ldg(bias + n + 1);
#pragma unroll
            for (int mi = 0; mi < 2; mi++) {
                acc[mi][ni][0] = b0; acc[mi][ni][1] = b1;
                acc[mi][ni][2] = b0; acc[mi][ni][3] = b1;
            }
        }
    }

    int g_row = tid >> 3;          // 0..31
    int g_c   = tid & 7;           // 0..7

#define ISSUE_B(it_)                                                              \
    do {                                                                          \
        uint32_t bb_ = sb + OFF_B((it_) & 1);                                     \
        const char* bgm_ = (const char*)(Bw + (size_t)n0 * KP + (it_) * BK);      \
        _Pragma("unroll")                                                         \
        for (int r_ = 0; r_ < 8; r_++) {                                          \
            int row_ = g_row + r_ * 32;                                           \
            uint32_t dst_ = bb_ + row_ * 128 + ((g_c ^ (row_ & 7)) << 4);         \
            cp_async16(dst_, bgm_ + (size_t)row_ * (KP * 2) + g_c * 16);          \
        }                                                                         \
    } while (0)

    ISSUE_B(0); CP_COMMIT();
    ISSUE_B(1); CP_COMMIT();
    gen_chunk(smem, x, 0, m0);
    __syncthreads();

    int lr = lid & 7;
    int lt = lid >> 3;

    for (int c = 0; c < NITER; c++) {
        CP_WAIT(1);
        __syncthreads();

        uint32_t abase = sb + OFF_A(c & 1);
        uint32_t bbase = sb + OFF_B(c & 1);

#pragma unroll
        for (int ks = 0; ks < 4; ks++) {
            uint32_t afr[2][4];
#pragma unroll
            for (int mi = 0; mi < 2; mi++) {
                int m = wm * 32 + mi * 16 + (lt & 1) * 8 + lr;
                int g = ks * 2 + (lt >> 1);
                ldsm_x4(afr[mi], abase + m * 128 + ((g ^ (m & 7)) << 4));
            }
#pragma unroll
            for (int nb = 0; nb < 8; nb++) {
                uint32_t bfr[4];
                int n = wn * 128 + nb * 16 + (lt & 1) * 8 + lr;
                int g = ks * 2 + (lt >> 1);
                ldsm_x4(bfr, bbase + n * 128 + ((g ^ (n & 7)) << 4));
#pragma unroll
                for (int h = 0; h < 2; h++)
#pragma unroll
                    for (int mi = 0; mi < 2; mi++)
                        mma16816(acc[mi][2 * nb + h], afr[mi], bfr[h], bfr[h + 2]);
            }
            // interleave A-generation for next chunk after first ks block
            if (ks == 0 && c + 1 < NITER) gen_chunk(smem, x, c + 1, m0);
        }

        __syncthreads();
        if (c + 2 < NITER) ISSUE_B(c + 2);
        CP_COMMIT();
    }

    // ---------------- epilogue ----------------
    int mrow = lid >> 2;
    int ncol = (lid & 3) * 2;
#pragma unroll
    for (int mi = 0; mi < 2; mi++) {
#pragma unroll
        for (int ni = 0; ni < 16; ni++) {
            int n = n0 + wn * 128 + ni * 8 + ncol;
            int m_lo = m0 + wm * 32 + mi * 16 + mrow;
            float2 v0, v1;
            v0.x = acc[mi][ni][0] * OUT_SCALE;
            v0.y = acc[mi][ni][1] * OUT_SCALE;
            v1.x = acc[mi][ni][2] * OUT_SCALE;
            v1.y = acc[mi][ni][3] * OUT_SCALE;
            *reinterpret_cast<float2*>(out + (size_t)m_lo * OUT_F + n) = v0;
            *reinterpret_cast<float2*>(out + (size_t)(m_lo + 8) * OUT_F + n) = v1;
        }
    }
#undef ISSUE_B
}

// ---------------- launch ------------------------------------------------------
extern "C" void kernel_launch(void* const* d_in, const int* in_sizes, int n_in,
                              void* d_out, int out_size) {
    const float* x     = (const float*)d_in[0];
    const float* coeff = (const float*)d_in[1];
    float* out = (float*)d_out;

    void* pB = nullptr;
    void* pBias = nullptr;
    cudaGetSymbolAddress(&pB, g_B);
    cudaGetSymbolAddress(&pBias, g_bias);

    gen_b_kernel<<<OUT_F, IN_F>>>(coeff, (__half*)pB, (float*)pBias);

    cudaFuncSetAttribute(gemm_kernel, cudaFuncAttributeMaxDynamicSharedMemorySize,
                         SMEM_TOTAL);
    dim3 grid(OUT_F / BN, BATCH / BM);   // (2, 256)
    gemm_kernel<<<grid, 256, SMEM_TOTAL>>>(x, (const __half*)pB,
                                           (const float*)pBias, out);
}

// round 9
// speedup vs baseline: 1.1383x; 1.1383x over previous
#include <cuda_runtime.h>
#include <cuda_fp16.h>
#include <cstdint>
#include <cstddef>

#define BATCH 32768
#define IN_F  512
#define OUT_F 512
#define KP    4096             // K' = IN_F * 8  (d = 1..8; d=0 folded into bias)

#define BM 128
#define BN 256
#define BK 64
#define NITER (KP / BK)        // 64
#define COEF_SCALE 4096.0f
#define OUT_SCALE  (1.0f / 4096.0f)

// ---------------- smem layout (bytes) ----------------------------------------
// B stages:   2 x 32768           [0, 65536)
// A bufs:     2 x 16384           [65536, 98304)
// u  (fp32):  128 rows x 272B     [98304, 133120)
// T0 (fp32):  128 rows x 272B     [133120, 167936)   (even-degree T)
// T1 (fp32):  128 rows x 272B     [167936, 202752)   (odd-degree T)
#define OFF_B(s) ((s) * 32768u)
#define OFF_A(p) (65536u + (p) * 16384u)
#define OFF_U    98304u
#define OFF_T0   133120u
#define OFF_T1   167936u
#define SMEM_TOTAL 202752

// ---------------- scratch ----------------------------------------------------
__device__ __align__(1024) __half g_B[(size_t)OUT_F * KP];   // 4 MB
__device__ float g_bias[OUT_F];

// ---------------- helpers ----------------------------------------------------
__device__ __forceinline__ uint32_t smem_u32(const void* p) {
    uint32_t a;
    asm("{ .reg .u64 t; cvta.to.shared.u64 t, %1; cvt.u32.u64 %0, t; }" : "=r"(a) : "l"(p));
    return a;
}
__device__ __forceinline__ uint32_t pack_h2(float lo, float hi) {
    uint32_t r;
    asm("cvt.rn.f16x2.f32 %0, %1, %2;" : "=r"(r) : "f"(hi), "f"(lo));
    return r;
}
__device__ __forceinline__ void cp_async16(uint32_t dst, const void* src) {
    asm volatile("cp.async.cg.shared.global [%0], [%1], 16;" :: "r"(dst), "l"(src) : "memory");
}
#define CP_COMMIT() asm volatile("cp.async.commit_group;" ::: "memory")
#define CP_WAIT(n)  asm volatile("cp.async.wait_group %0;" :: "n"(n) : "memory")

__device__ __forceinline__ void ldsm_x4(uint32_t f[4], uint32_t addr) {
    asm volatile("ldmatrix.sync.aligned.m8n8.x4.shared.b16 {%0,%1,%2,%3}, [%4];"
                 : "=r"(f[0]), "=r"(f[1]), "=r"(f[2]), "=r"(f[3]) : "r"(addr));
}
__device__ __forceinline__ void mma16816(float c[4], const uint32_t a[4],
                                         uint32_t b0, uint32_t b1) {
    asm volatile(
        "mma.sync.aligned.m16n8k16.row.col.f32.f16.f16.f32 "
        "{%0,%1,%2,%3}, {%4,%5,%6,%7}, {%8,%9}, {%0,%1,%2,%3};"
        : "+f"(c[0]), "+f"(c[1]), "+f"(c[2]), "+f"(c[3])
        : "r"(a[0]), "r"(a[1]), "r"(a[2]), "r"(a[3]), "r"(b0), "r"(b1));
}

// ---------------- gen_b: B'[o, iblk*512+(d-1)*64+ii] = 4096*C[i,o,d]; bias ---
__global__ void gen_b_kernel(const float* __restrict__ c, __half* __restrict__ B,
                             float* __restrict__ bias) {
    __shared__ float red[IN_F];
    int o = blockIdx.x;
    int i = threadIdx.x;                  // 0..511
    const float* src = c + ((size_t)i * OUT_F + o) * 9;
    red[i] = src[0];
    __half* dst = B + (size_t)o * KP + (i >> 6) * 512 + (i & 63);
#pragma unroll
    for (int d = 1; d <= 8; d++)
        dst[(d - 1) * 64] = __float2half_rn(src[d] * COEF_SCALE);
    __syncthreads();
#pragma unroll
    for (int s = IN_F / 2; s > 0; s >>= 1) {
        if (i < s) red[i] += red[i + s];
        __syncthreads();
    }
    if (i == 0) bias[o] = red[0] * COEF_SCALE;
}

// ---------------- A-chunk generation (gen warps only; 128 threads) -----------
// chunk c1: iblk = c1>>3, d = (c1&7)+1.  A[m][ii] = T_d(tanh(x[m0+m][iblk*64+ii]))
// one thread per M-row (gtid = 0..127), 64 elements each.
__device__ __forceinline__ void gen_chunk_ws(char* sm, const float* __restrict__ xg,
                                             int c1, int m0, int gtid) {
    int m = gtid;
    int d    = (c1 & 7) + 1;
    int iblk = c1 >> 3;
    char* arow  = sm + OFF_A(c1 & 1) + m * 128;
    char* urow  = sm + OFF_U  + m * 272;
    char* t0row = sm + OFF_T0 + m * 272;
    char* t1row = sm + OFF_T1 + m * 272;
    int sw = (m & 7) << 4;
    if (d == 1) {
        const float* xp = xg + (size_t)(m0 + m) * IN_F + iblk * 64;
#pragma unroll
        for (int j = 0; j < 8; j++) {
            float4 xa = *reinterpret_cast<const float4*>(xp + j * 8);
            float4 xb = *reinterpret_cast<const float4*>(xp + j * 8 + 4);
            float4 ua, ub;
            ua.x = tanhf(xa.x); ua.y = tanhf(xa.y); ua.z = tanhf(xa.z); ua.w = tanhf(xa.w);
            ub.x = tanhf(xb.x); ub.y = tanhf(xb.y); ub.z = tanhf(xb.z); ub.w = tanhf(xb.w);
            *reinterpret_cast<float4*>(urow + j * 32)       = ua;
            *reinterpret_cast<float4*>(urow + j * 32 + 16)  = ub;
            *reinterpret_cast<float4*>(t1row + j * 32)      = ua;   // T1 = u
            *reinterpret_cast<float4*>(t1row + j * 32 + 16) = ub;
            uint4 h;
            h.x = pack_h2(ua.x, ua.y); h.y = pack_h2(ua.z, ua.w);
            h.z = pack_h2(ub.x, ub.y); h.w = pack_h2(ub.z, ub.w);
            *reinterpret_cast<uint4*>(arow + ((j << 4) ^ sw)) = h;
        }
    } else if (d == 2) {
        // T2 = 2u*u - 1
#pragma unroll
        for (int j = 0; j < 8; j++) {
            float4 ua = *reinterpret_cast<const float4*>(urow + j * 32);
            float4 ub = *reinterpret_cast<const float4*>(urow + j * 32 + 16);
            float4 na, nb;
            na.x = __fmaf_rn(2.f * ua.x, ua.x, -1.f);
            na.y = __fmaf_rn(2.f * ua.y, ua.y, -1.f);
            na.z = __fmaf_rn(2.f * ua.z, ua.z, -1.f);
            na.w = __fmaf_rn(2.f * ua.w, ua.w, -1.f);
            nb.x = __fmaf_rn(2.f * ub.x, ub.x, -1.f);
            nb.y = __fmaf_rn(2.f * ub.y, ub.y, -1.f);
            nb.z = __fmaf_rn(2.f * ub.z, ub.z, -1.f);
            nb.w = __fmaf_rn(2.f * ub.w, ub.w, -1.f);
            *reinterpret_cast<float4*>(t0row + j * 32)      = na;
            *reinterpret_cast<float4*>(t0row + j * 32 + 16) = nb;
            uint4 h;
            h.x = pack_h2(na.x, na.y); h.y = pack_h2(na.z, na.w);
            h.z = pack_h2(nb.x, nb.y); h.w = pack_h2(nb.z, nb.w);
            *reinterpret_cast<uint4*>(arow + ((j << 4) ^ sw)) = h;
        }
    } else {
        // d odd:  Tc = T_{d-1} (even) in t0, Tp = T_{d-2} (odd) in t1, Tn -> t1
        // d even: Tc in t1, Tp in t0, Tn -> t0
        char* tcrow = (d & 1) ? t0row : t1row;
        char* tprow = (d & 1) ? t1row : t0row;
#pragma unroll
        for (int j = 0; j < 8; j++) {
            float4 ua = *reinterpret_cast<const float4*>(urow + j * 32);
            float4 ub = *reinterpret_cast<const float4*>(urow + j * 32 + 16);
            float4 ca = *reinterpret_cast<const float4*>(tcrow + j * 32);
            float4 cb = *reinterpret_cast<const float4*>(tcrow + j * 32 + 16);
            float4 pa = *reinterpret_cast<const float4*>(tprow + j * 32);
            float4 pb = *reinterpret_cast<const float4*>(tprow + j * 32 + 16);
            float4 na, nb;
            na.x = __fmaf_rn(2.f * ua.x, ca.x, -pa.x);
            na.y = __fmaf_rn(2.f * ua.y, ca.y, -pa.y);
            na.z = __fmaf_rn(2.f * ua.z, ca.z, -pa.z);
            na.w = __fmaf_rn(2.f * ua.w, ca.w, -pa.w);
            nb.x = __fmaf_rn(2.f * ub.x, cb.x, -pb.x);
            nb.y = __fmaf_rn(2.f * ub.y, cb.y, -pb.y);
            nb.z = __fmaf_rn(2.f * ub.z, cb.z, -pb.z);
            nb.w = __fmaf_rn(2.f * ub.w, cb.w, -pb.w);
            *reinterpret_cast<float4*>(tprow + j * 32)      = na;
            *reinterpret_cast<float4*>(tprow + j * 32 + 16) = nb;
            uint4 h;
            h.x = pack_h2(na.x, na.y); h.y = pack_h2(na.z, na.w);
            h.z = pack_h2(nb.x, nb.y); h.w = pack_h2(nb.z, nb.w);
            *reinterpret_cast<uint4*>(arow + ((j << 4) ^ sw)) = h;
        }
    }
}

// ---------------- fused warp-specialized GEMM: M=32768 N=512 K'=4096 ---------
// warps 0..7 : pure ldmatrix+mma mainloop (R3 structure)
// warps 8..11: A generation + B cp.async production
__global__ __launch_bounds__(384, 1)
void gemm_kernel(const float* __restrict__ x, const __half* __restrict__ Bw,
                 const float* __restrict__ bias, float* __restrict__ out) {
    extern __shared__ __align__(1024) char smem[];
    uint32_t sb = smem_u32(smem);
    int tid = threadIdx.x;
    int wid = tid >> 5, lid = tid & 31;
    int m0 = blockIdx.y * BM;
    int n0 = blockIdx.x * BN;
    bool is_gen = (wid >= 8);
    int gtid = tid - 256;          // 0..127 for gen warps
    int wm = wid & 3, wn = wid >> 2;

    float acc[2][16][4];

    int g_c = gtid & 7;            // 16B col for cp.async (gen threads)

#define ISSUE_B_G(it_)                                                            \
    do {                                                                          \
        uint32_t bb_ = sb + OFF_B((it_) & 1);                                     \
        const char* bgm_ = (const char*)(Bw + (size_t)n0 * KP + (it_) * BK);      \
        _Pragma("unroll")                                                         \
        for (int r_ = 0; r_ < 16; r_++) {                                         \
            int row_ = (gtid >> 3) + r_ * 16;                                     \
            uint32_t dst_ = bb_ + row_ * 128 + ((g_c ^ (row_ & 7)) << 4);         \
            cp_async16(dst_, bgm_ + (size_t)row_ * (KP * 2) + g_c * 16);          \
        }                                                                         \
    } while (0)

    if (is_gen) {
        ISSUE_B_G(0); CP_COMMIT();
        ISSUE_B_G(1); CP_COMMIT();
        gen_chunk_ws(smem, x, 0, m0, gtid);
        CP_WAIT(1);                 // B0 landed
    } else {
        // acc init = bias (T_0 contribution, pre-scaled by 4096)
        int ncol = (lid & 3) * 2;
#pragma unroll
        for (int ni = 0; ni < 16; ni++) {
            int n = n0 + wn * 128 + ni * 8 + ncol;
            float b0 = __ldg(bias + n);
            float b1 = __ldg(bias + n + 1);
#pragma unroll
            for (int mi = 0; mi < 2; mi++) {
                acc[mi][ni][0] = b0; acc[mi][ni][1] = b1;
                acc[mi][ni][2] = b0; acc[mi][ni][3] = b1;
            }
        }
    }
    __syncthreads();

    int lr = lid & 7;
    int lt = lid >> 3;

    for (int c = 0; c < NITER; c++) {
        if (is_gen) {
            if (c + 1 < NITER) gen_chunk_ws(smem, x, c + 1, m0, gtid);
        } else {
            uint32_t abase = sb + OFF_A(c & 1);
            uint32_t bbase = sb + OFF_B(c & 1);
#pragma unroll
            for (int ks = 0; ks < 4; ks++) {
                uint32_t afr[2][4];
#pragma unroll
                for (int mi = 0; mi < 2; mi++) {
                    int m = wm * 32 + mi * 16 + (lt & 1) * 8 + lr;
                    int g = ks * 2 + (lt >> 1);
                    ldsm_x4(afr[mi], abase + m * 128 + ((g ^ (m & 7)) << 4));
                }
#pragma unroll
                for (int nb = 0; nb < 8; nb++) {
                    uint32_t bfr[4];
                    int n = wn * 128 + nb * 16 + (lt & 1) * 8 + lr;
                    int g = ks * 2 + (lt >> 1);
                    ldsm_x4(bfr, bbase + n * 128 + ((g ^ (n & 7)) << 4));
#pragma unroll
                    for (int h = 0; h < 2; h++)
#pragma unroll
                        for (int mi = 0; mi < 2; mi++)
                            mma16816(acc[mi][2 * nb + h], afr[mi], bfr[h], bfr[h + 2]);
                }
            }
        }
        __syncthreads();   // MMA done reading A[c],B[c]; gen done writing A[c+1]
        if (is_gen) {
            if (c + 2 < NITER) ISSUE_B_G(c + 2);
            CP_COMMIT();
            CP_WAIT(1);    // B[c+1] landed
        }
        __syncthreads();
    }

    // ---------------- epilogue (MMA warps only) ----------------
    if (!is_gen) {
        int mrow = lid >> 2;
        int ncol = (lid & 3) * 2;
#pragma unroll
        for (int mi = 0; mi < 2; mi++) {
#pragma unroll
            for (int ni = 0; ni < 16; ni++) {
                int n = n0 + wn * 128 + ni * 8 + ncol;
                int m_lo = m0 + wm * 32 + mi * 16 + mrow;
                float2 v0, v1;
                v0.x = acc[mi][ni][0] * OUT_SCALE;
                v0.y = acc[mi][ni][1] * OUT_SCALE;
                v1.x = acc[mi][ni][2] * OUT_SCALE;
                v1.y = acc[mi][ni][3] * OUT_SCALE;
                *reinterpret_cast<float2*>(out + (size_t)m_lo * OUT_F + n) = v0;
                *reinterpret_cast<float2*>(out + (size_t)(m_lo + 8) * OUT_F + n) = v1;
            }
        }
    }
#undef ISSUE_B_G
}

// ---------------- launch ------------------------------------------------------
extern "C" void kernel_launch(void* const* d_in, const int* in_sizes, int n_in,
                              void* d_out, int out_size) {
    const float* x     = (const float*)d_in[0];
    const float* coeff = (const float*)d_in[1];
    float* out = (float*)d_out;

    void* pB = nullptr;
    void* pBias = nullptr;
    cudaGetSymbolAddress(&pB, g_B);
    cudaGetSymbolAddress(&pBias, g_bias);

    gen_b_kernel<<<OUT_F, IN_F>>>(coeff, (__half*)pB, (float*)pBias);

    cudaFuncSetAttribute(gemm_kernel, cudaFuncAttributeMaxDynamicSharedMemorySize,
                         SMEM_TOTAL);
    dim3 grid(OUT_F / BN, BATCH / BM);   // (2, 256)
    gemm_kernel<<<grid, 384, SMEM_TOTAL>>>(x, (const __half*)pB,
                                           (const float*)pBias, out);
}